// round 16
// baseline (speedup 1.0000x reference)
#include <cuda_runtime.h>
#include <cuda_fp16.h>

// ---------------------------------------------------------------------------
// TFConvBertSelfAttention  (B=4, S=2048, C=768, H=6, D=64, AHS=384, K=9)
// R16: attention softmax in log2 domain — Q pre-scaled by log2e/8, mask
//      staged in smem pre-scaled, packed ex2.approx.f16x2, l-sum via an
//      all-ones mma column (fp32 tensor-core accumulation, no shuffles).
// ---------------------------------------------------------------------------

#define BATCH   4
#define SEQ     2048
#define CIN     768
#define NHEAD   6
#define HDIM    64
#define AHS     384
#define KTAPS   9
#define MROWS   (BATCH * SEQ)          // 8192

// ------------------------- scratch (static device mem) ---------------------
__device__ float    g_q [MROWS * AHS];
__device__ unsigned g_kt[MROWS * (AHS / 2)];
__device__ unsigned g_vtT[AHS * (MROWS / 2)];
__device__ float    g_co[MROWS * AHS];
__device__ float    g_kc[MROWS * AHS];
__device__ float    g_dw[MROWS * CIN];
__device__ float    g_ck[MROWS * 64];

// ------------------------- streams/events (host, created once) -------------
static cudaStream_t g_s2;
static cudaEvent_t  g_evFork, g_evJoin;
namespace {
struct StreamInit {
    StreamInit() {
        cudaStreamCreateWithFlags(&g_s2, cudaStreamNonBlocking);
        cudaEventCreateWithFlags(&g_evFork, cudaEventDisableTiming);
        cudaEventCreateWithFlags(&g_evJoin, cudaEventDisableTiming);
    }
};
static StreamInit g_streamInit;
}

// ------------------------- helpers -----------------------------------------
__device__ __forceinline__ unsigned f2h2(float lo, float hi) {
    unsigned r;
    asm("cvt.rn.f16x2.f32 %0, %1, %2;" : "=r"(r) : "f"(hi), "f"(lo));
    return r;
}

__device__ __forceinline__ unsigned ex2_h2(unsigned x) {
    unsigned r;
    asm("ex2.approx.f16x2 %0, %1;" : "=r"(r) : "r"(x));
    return r;
}

__device__ __forceinline__ void mma_f16(float* c, const unsigned* a,
                                        unsigned b0, unsigned b1) {
    asm volatile(
        "mma.sync.aligned.m16n8k16.row.col.f32.f16.f16.f32 "
        "{%0,%1,%2,%3}, {%4,%5,%6,%7}, {%8,%9}, {%0,%1,%2,%3};\n"
        : "+f"(c[0]), "+f"(c[1]), "+f"(c[2]), "+f"(c[3])
        : "r"(a[0]), "r"(a[1]), "r"(a[2]), "r"(a[3]), "r"(b0), "r"(b1));
}

__device__ __forceinline__ void cpa16(void* sm, const void* g) {
    unsigned sa = (unsigned)__cvta_generic_to_shared(sm);
    asm volatile("cp.async.cg.shared.global [%0], [%1], 16;" :: "r"(sa), "l"(g));
}

// ------------------------- fp16 GEMM, z = blockIdx.z + zbase ----------------
__global__ __launch_bounds__(128)
void gemm4_f16(const float* __restrict__ A,
               const float* __restrict__ W0, const float* __restrict__ W1,
               const float* __restrict__ W2, const float* __restrict__ W3,
               const float* __restrict__ b0, const float* __restrict__ b1,
               const float* __restrict__ b2, const float* __restrict__ b3,
               float* __restrict__ Oq, unsigned* __restrict__ Okt,
               unsigned* __restrict__ OvtT, float* __restrict__ Oco,
               int zbase)
{
    const float* Ws[4] = {W0, W1, W2, W3};
    const float* bs[4] = {b0, b1, b2, b3};
    const int z = blockIdx.z + zbase;
    const float* B = Ws[z];
    const float* bias = bs[z];

    __shared__ unsigned Ash[2][64][20];
    __shared__ unsigned Bsh[2][16][72];

    const int tid  = threadIdx.x;
    const int warp = tid >> 5;
    const int lane = tid & 31;
    const int g    = lane >> 2;
    const int tq   = lane & 3;
    const int m0 = blockIdx.y * 64;
    const int n0 = blockIdx.x * 64;

    float acc[8][4];
#pragma unroll
    for (int nc = 0; nc < 8; nc++)
#pragma unroll
        for (int i = 0; i < 4; i++) acc[nc][i] = 0.f;

    const int a_k4 = (tid & 7) * 4;
    const int a_rb = tid >> 3;
    const int b_kp = tid >> 4;
    const int b_c4 = (tid & 15) * 4;

    float4 ar[4];
    float4 br[2][2];

#pragma unroll
    for (int p = 0; p < 4; p++)
        ar[p] = *(const float4*)(A + (size_t)(m0 + a_rb + 16 * p) * CIN + a_k4);
#pragma unroll
    for (int p = 0; p < 2; p++) {
        const int kp = b_kp + 8 * p;
        br[p][0] = *(const float4*)(B + (size_t)(2 * kp)     * AHS + n0 + b_c4);
        br[p][1] = *(const float4*)(B + (size_t)(2 * kp + 1) * AHS + n0 + b_c4);
    }
#pragma unroll
    for (int p = 0; p < 4; p++) {
        const int row = a_rb + 16 * p;
        Ash[0][row][a_k4 / 2]     = f2h2(ar[p].x, ar[p].y);
        Ash[0][row][a_k4 / 2 + 1] = f2h2(ar[p].z, ar[p].w);
    }
#pragma unroll
    for (int p = 0; p < 2; p++) {
        const int kp = b_kp + 8 * p;
        Bsh[0][kp][b_c4 + 0] = f2h2(br[p][0].x, br[p][1].x);
        Bsh[0][kp][b_c4 + 1] = f2h2(br[p][0].y, br[p][1].y);
        Bsh[0][kp][b_c4 + 2] = f2h2(br[p][0].z, br[p][1].z);
        Bsh[0][kp][b_c4 + 3] = f2h2(br[p][0].w, br[p][1].w);
    }
    __syncthreads();

    const int NIT = CIN / 32;
    for (int it = 0; it < NIT; it++) {
        const int cur = it & 1;
        const bool more = (it + 1 < NIT);

        if (more) {
            const int k0 = (it + 1) * 32;
#pragma unroll
            for (int p = 0; p < 4; p++)
                ar[p] = *(const float4*)(A + (size_t)(m0 + a_rb + 16 * p) * CIN + k0 + a_k4);
#pragma unroll
            for (int p = 0; p < 2; p++) {
                const int kp = b_kp + 8 * p;
                br[p][0] = *(const float4*)(B + (size_t)(k0 + 2 * kp)     * AHS + n0 + b_c4);
                br[p][1] = *(const float4*)(B + (size_t)(k0 + 2 * kp + 1) * AHS + n0 + b_c4);
            }
        }

#pragma unroll
        for (int kcc = 0; kcc < 2; kcc++) {
            unsigned a[4];
            a[0] = Ash[cur][warp * 16 + g    ][kcc * 8 + tq    ];
            a[1] = Ash[cur][warp * 16 + g + 8][kcc * 8 + tq    ];
            a[2] = Ash[cur][warp * 16 + g    ][kcc * 8 + tq + 4];
            a[3] = Ash[cur][warp * 16 + g + 8][kcc * 8 + tq + 4];
#pragma unroll
            for (int nc = 0; nc < 8; nc++)
                mma_f16(acc[nc], a,
                        Bsh[cur][kcc * 8 + tq    ][nc * 8 + g],
                        Bsh[cur][kcc * 8 + tq + 4][nc * 8 + g]);
        }

        if (more) {
            const int nxt = cur ^ 1;
#pragma unroll
            for (int p = 0; p < 4; p++) {
                const int row = a_rb + 16 * p;
                Ash[nxt][row][a_k4 / 2]     = f2h2(ar[p].x, ar[p].y);
                Ash[nxt][row][a_k4 / 2 + 1] = f2h2(ar[p].z, ar[p].w);
            }
#pragma unroll
            for (int p = 0; p < 2; p++) {
                const int kp = b_kp + 8 * p;
                Bsh[nxt][kp][b_c4 + 0] = f2h2(br[p][0].x, br[p][1].x);
                Bsh[nxt][kp][b_c4 + 1] = f2h2(br[p][0].y, br[p][1].y);
                Bsh[nxt][kp][b_c4 + 2] = f2h2(br[p][0].z, br[p][1].z);
                Bsh[nxt][kp][b_c4 + 3] = f2h2(br[p][0].w, br[p][1].w);
            }
        }
        __syncthreads();
    }

    const int r0 = m0 + warp * 16 + g;
    if (z == 0 || z == 3) {
        float* C = (z == 0) ? Oq : Oco;
#pragma unroll
        for (int nc = 0; nc < 8; nc++) {
            const int col = n0 + nc * 8 + 2 * tq;
            const float bv0 = bias[col], bv1 = bias[col + 1];
            *(float2*)(C + (size_t)r0 * AHS + col) =
                make_float2(acc[nc][0] + bv0, acc[nc][1] + bv1);
            *(float2*)(C + (size_t)(r0 + 8) * AHS + col) =
                make_float2(acc[nc][2] + bv0, acc[nc][3] + bv1);
        }
    } else if (z == 1) {
#pragma unroll
        for (int nc = 0; nc < 8; nc++) {
            const int col = n0 + nc * 8 + 2 * tq;
            const float bv0 = bias[col], bv1 = bias[col + 1];
            const int wp = n0 / 2 + (nc >> 1) * 8 + 2 * tq + (nc & 1);
            Okt[(size_t)r0 * (AHS / 2) + wp]       = f2h2(acc[nc][0] + bv0, acc[nc][1] + bv1);
            Okt[(size_t)(r0 + 8) * (AHS / 2) + wp] = f2h2(acc[nc][2] + bv0, acc[nc][3] + bv1);
        }
    } else {
#pragma unroll
        for (int nc = 0; nc < 8; nc++) {
            const int col = n0 + nc * 8 + 2 * tq;
            const float bv0 = bias[col], bv1 = bias[col + 1];
            const unsigned ulo = f2h2(acc[nc][0] + bv0, acc[nc][1] + bv1);
            const unsigned uhi = f2h2(acc[nc][2] + bv0, acc[nc][3] + bv1);
            const unsigned plo = __shfl_xor_sync(0xffffffffu, ulo, 4);
            const unsigned phi = __shfl_xor_sync(0xffffffffu, uhi, 4);
            if ((g & 1) == 0) {
                const unsigned w0lo = (ulo & 0xFFFFu) | (plo << 16);
                const unsigned w1lo = (ulo >> 16)     | (plo & 0xFFFF0000u);
                const unsigned w0hi = (uhi & 0xFFFFu) | (phi << 16);
                const unsigned w1hi = (uhi >> 16)     | (phi & 0xFFFF0000u);
                const size_t base = (size_t)(m0 / 2 + warp * 8 + g);
                *(uint2*)(OvtT + (size_t)col * (MROWS / 2) + base) =
                    make_uint2(w0lo, w0hi);
                *(uint2*)(OvtT + (size_t)(col + 1) * (MROWS / 2) + base) =
                    make_uint2(w1lo, w1hi);
            }
        }
    }
}

// ------------------------- depthwise conv, smem tiled ----------------------
__global__ __launch_bounds__(256)
void dwconv9s(const float* __restrict__ hs, const float* __restrict__ w,
              float* __restrict__ out)
{
    __shared__ float tile[40][256];
    const int tid = threadIdx.x;
    const int c0  = blockIdx.x * 256;
    const int row0 = blockIdx.y * 32;
    const int b = row0 >> 11;
    const int s0 = row0 & (SEQ - 1);

    for (int i = tid; i < 40 * 256; i += 256) {
        const int r = i >> 8, c = i & 255;
        const int ss = s0 + r - 4;
        tile[r][c] = (ss >= 0 && ss < SEQ)
            ? hs[(size_t)(b * SEQ + ss) * CIN + c0 + c] : 0.f;
    }
    float wr[KTAPS];
#pragma unroll
    for (int t = 0; t < KTAPS; t++) wr[t] = w[t * CIN + c0 + tid];
    __syncthreads();

#pragma unroll 4
    for (int si = 0; si < 32; si++) {
        float acc = 0.f;
#pragma unroll
        for (int t = 0; t < KTAPS; t++)
            acc = fmaf(tile[si + t][tid], wr[t], acc);
        out[(size_t)(row0 + si) * CIN + c0 + tid] = acc;
    }
}

// ---------------- span GEMM: logits = (kc*q) @ Wck + bck -------------------
struct SpanSmem {
    unsigned As[64][20];
    unsigned Bw[192][56];
};

__global__ __launch_bounds__(128)
void span_gemm(const float* __restrict__ kcv, const float* __restrict__ q,
               const float* __restrict__ Wck, const float* __restrict__ bck,
               float* __restrict__ ck)
{
    extern __shared__ char smem_raw[];
    SpanSmem& sm = *reinterpret_cast<SpanSmem*>(smem_raw);

    const int tid  = threadIdx.x;
    const int warp = tid >> 5;
    const int lane = tid & 31;
    const int g    = lane >> 2;
    const int tq   = lane & 3;
    const int m0 = blockIdx.x * 64;
    const int NCK = NHEAD * KTAPS;   // 54

    for (int idx = tid; idx < 192 * NCK; idx += 128) {
        const int kp = idx / NCK, c = idx % NCK;
        sm.Bw[kp][c] = f2h2(Wck[(size_t)(2 * kp) * NCK + c],
                            Wck[(size_t)(2 * kp + 1) * NCK + c]);
    }
    for (int idx = tid; idx < 192 * 2; idx += 128)
        sm.Bw[idx >> 1][54 + (idx & 1)] = 0u;

    float acc[7][4];
#pragma unroll
    for (int nc = 0; nc < 7; nc++)
#pragma unroll
        for (int i = 0; i < 4; i++) acc[nc][i] = 0.f;

    const int a_k4 = (tid & 7) * 4;
    const int a_rb = tid >> 3;

    float4 xr[4], qr[4];
#pragma unroll
    for (int p = 0; p < 4; p++) {
        const size_t off = (size_t)(m0 + a_rb + 16 * p) * AHS + a_k4;
        xr[p] = *(const float4*)(kcv + off);
        qr[p] = *(const float4*)(q + off);
    }

    for (int k0 = 0; k0 < AHS; k0 += 32) {
#pragma unroll
        for (int p = 0; p < 4; p++) {
            const int row = a_rb + 16 * p;
            sm.As[row][a_k4 / 2]     = f2h2(xr[p].x * qr[p].x, xr[p].y * qr[p].y);
            sm.As[row][a_k4 / 2 + 1] = f2h2(xr[p].z * qr[p].z, xr[p].w * qr[p].w);
        }
        __syncthreads();

        if (k0 + 32 < AHS) {
#pragma unroll
            for (int p = 0; p < 4; p++) {
                const size_t off = (size_t)(m0 + a_rb + 16 * p) * AHS + k0 + 32 + a_k4;
                xr[p] = *(const float4*)(kcv + off);
                qr[p] = *(const float4*)(q + off);
            }
        }

#pragma unroll
        for (int kcc = 0; kcc < 2; kcc++) {
            unsigned a[4];
            a[0] = sm.As[warp * 16 + g    ][kcc * 8 + tq    ];
            a[1] = sm.As[warp * 16 + g + 8][kcc * 8 + tq    ];
            a[2] = sm.As[warp * 16 + g    ][kcc * 8 + tq + 4];
            a[3] = sm.As[warp * 16 + g + 8][kcc * 8 + tq + 4];
            const int kpb = k0 / 2 + kcc * 8;
#pragma unroll
            for (int nc = 0; nc < 7; nc++)
                mma_f16(acc[nc], a,
                        sm.Bw[kpb + tq    ][nc * 8 + g],
                        sm.Bw[kpb + tq + 4][nc * 8 + g]);
        }
        __syncthreads();
    }

    const int r0 = m0 + warp * 16 + g;
#pragma unroll
    for (int nc = 0; nc < 7; nc++) {
        const int col = nc * 8 + 2 * tq;
        if (col < NCK) {
            const float bv0 = bck[col], bv1 = bck[col + 1];
            ck[(size_t)r0 * 64 + col]           = acc[nc][0] + bv0;
            ck[(size_t)r0 * 64 + col + 1]       = acc[nc][1] + bv1;
            ck[(size_t)(r0 + 8) * 64 + col]     = acc[nc][2] + bv0;
            ck[(size_t)(r0 + 8) * 64 + col + 1] = acc[nc][3] + bv1;
        }
    }
}

// ---------------- softmax + dynamic conv (smem tiled) ----------------------
struct DynSmem {
    float cot[40][384];
    float p[32][56];
};

__global__ __launch_bounds__(384)
void dynsoft2(const float* __restrict__ ckraw, const float* __restrict__ co,
              float* __restrict__ out)
{
    extern __shared__ char smem_raw[];
    DynSmem& sm = *reinterpret_cast<DynSmem*>(smem_raw);
    const int tid = threadIdx.x;
    const int row0 = blockIdx.x * 32;
    const int b = row0 >> 11;
    const int s0 = row0 & (SEQ - 1);

    for (int j = 0; j < 40; j++) {
        const int ss = s0 + j - 4;
        sm.cot[j][tid] = (ss >= 0 && ss < SEQ)
            ? co[(size_t)(b * SEQ + ss) * AHS + tid] : 0.f;
    }
    if (tid < 32 * NHEAD) {
        const int r = tid / NHEAD, h = tid % NHEAD;
        const float* lr = ckraw + (size_t)(row0 + r) * 64 + h * KTAPS;
        float m = -1e30f;
#pragma unroll
        for (int t = 0; t < KTAPS; t++) m = fmaxf(m, lr[t]);
        float e[KTAPS], s = 0.f;
#pragma unroll
        for (int t = 0; t < KTAPS; t++) { e[t] = __expf(lr[t] - m); s += e[t]; }
        const float inv = 1.f / s;
#pragma unroll
        for (int t = 0; t < KTAPS; t++) sm.p[r][h * KTAPS + t] = e[t] * inv;
    }
    __syncthreads();

    const int h = tid >> 6;
#pragma unroll 4
    for (int si = 0; si < 32; si++) {
        float acc = 0.f;
#pragma unroll
        for (int t = 0; t < KTAPS; t++)
            acc = fmaf(sm.p[si][h * KTAPS + t], sm.cot[si + t][tid], acc);
        out[(size_t)(row0 + si) * (2 * AHS) + AHS + tid] = acc;
    }
}

// ---------------- flash attention (fp16 mma, log2-domain softmax) ----------
struct AttnSmem {
    unsigned Ks[2][64][40];
    unsigned Vs[2][64][40];
    float    Ms[SEQ];          // mask row pre-scaled by log2e
};

__global__ __launch_bounds__(256, 2)
void attn_f16(const float* __restrict__ q, const unsigned* __restrict__ kt,
              const unsigned* __restrict__ vtT, const float* __restrict__ mask,
              const float* __restrict__ headmask, float* __restrict__ out)
{
    extern __shared__ char smem_raw[];
    AttnSmem& sm = *reinterpret_cast<AttnSmem*>(smem_raw);

    const int tid  = threadIdx.x;
    const int warp = tid >> 5;
    const int lane = tid & 31;
    const int g    = lane >> 2;
    const int tq   = lane & 3;

    const int bh = blockIdx.y;
    const int b = bh / NHEAD, h = bh % NHEAD;
    const int q0 = blockIdx.x * 128;
    const int bS = b * SEQ;

    const float LOG2E = 1.4426950408889634f;

    // mask row -> smem, pre-scaled by log2e
    for (int i = tid; i < SEQ; i += 256)
        sm.Ms[i] = mask[(size_t)bS + i] * LOG2E;

    // Q fragments, scaled by log2e / sqrt(D)
    unsigned aq[4][4];
    {
        const float* qp = q + (size_t)(bS + q0 + warp * 16) * AHS + h * HDIM;
        const float s = 0.125f * LOG2E;
#pragma unroll
        for (int kc = 0; kc < 4; kc++) {
            const int c0 = kc * 16 + 2 * tq;
            aq[kc][0] = f2h2(qp[(size_t)g       * AHS + c0]     * s, qp[(size_t)g       * AHS + c0 + 1] * s);
            aq[kc][1] = f2h2(qp[(size_t)(g + 8) * AHS + c0]     * s, qp[(size_t)(g + 8) * AHS + c0 + 1] * s);
            aq[kc][2] = f2h2(qp[(size_t)g       * AHS + c0 + 8] * s, qp[(size_t)g       * AHS + c0 + 9] * s);
            aq[kc][3] = f2h2(qp[(size_t)(g + 8) * AHS + c0 + 8] * s, qp[(size_t)(g + 8) * AHS + c0 + 9] * s);
        }
    }

    float o[8][4];
#pragma unroll
    for (int nc = 0; nc < 8; nc++)
#pragma unroll
        for (int i = 0; i < 4; i++) o[nc][i] = 0.f;
    float lacc[4] = {0.f, 0.f, 0.f, 0.f};   // l via ones-column mma
    const unsigned ONES = 0x3C003C00u;       // half2(1,1)

#define ISSUE_KV(ibv, kbv) do {                                                  \
        _Pragma("unroll")                                                        \
        for (int cc = 0; cc < 2; cc++) {                                         \
            const int ch = tid + cc * 256;                                       \
            const int rr = ch >> 3, seg = (ch & 7) * 4;                          \
            cpa16(&sm.Ks[ibv][rr][seg],                                          \
                  kt + (size_t)(bS + (kbv) + rr) * (AHS / 2) + h * 32 + seg);    \
            cpa16(&sm.Vs[ibv][rr][seg],                                          \
                  vtT + (size_t)(h * 64 + rr) * (MROWS / 2) + (bS + (kbv)) / 2 + seg); \
        }                                                                        \
        asm volatile("cp.async.commit_group;");                                  \
    } while (0)

    ISSUE_KV(0, 0);

    for (int kb = 0; kb < SEQ; kb += 64) {
        asm volatile("cp.async.wait_group 0;");
        __syncthreads();
        const int ibuf = (kb >> 6) & 1;
        if (kb + 64 < SEQ) ISSUE_KV(ibuf ^ 1, kb + 64);

        // ---- scores (log2 domain) ----
        float sfr[8][4];
#pragma unroll
        for (int nc = 0; nc < 8; nc++) {
            sfr[nc][0] = sfr[nc][1] = sfr[nc][2] = sfr[nc][3] = 0.f;
#pragma unroll
            for (int kc = 0; kc < 4; kc++) {
                uint2 bb = *(const uint2*)&sm.Ks[ibuf][nc * 8 + g][kc * 8 + 2 * tq];
                mma_f16(sfr[nc], aq[kc], bb.x, bb.y);
            }
            float2 mv = *(const float2*)&sm.Ms[kb + nc * 8 + 2 * tq];
            sfr[nc][0] += mv.x; sfr[nc][1] += mv.y;
            sfr[nc][2] += mv.x; sfr[nc][3] += mv.y;
        }

        // ---- P = 2^s, packed fp16 ----
        unsigned Pu0[8], Pu1[8];
#pragma unroll
        for (int nc = 0; nc < 8; nc++) {
            Pu0[nc] = ex2_h2(f2h2(sfr[nc][0], sfr[nc][1]));
            Pu1[nc] = ex2_h2(f2h2(sfr[nc][2], sfr[nc][3]));
        }

        // ---- PV (+ l via ones column) ----
#pragma unroll
        for (int kc = 0; kc < 4; kc++) {
            unsigned ap[4];
            ap[0] = Pu0[2 * kc];
            ap[1] = Pu1[2 * kc];
            ap[2] = Pu0[2 * kc + 1];
            ap[3] = Pu1[2 * kc + 1];
#pragma unroll
            for (int nd = 0; nd < 8; nd++) {
                uint2 vv = *(const uint2*)&sm.Vs[ibuf][nd * 8 + g][kc * 8 + 2 * tq];
                mma_f16(o[nd], ap, vv.x, vv.y);
            }
            mma_f16(lacc, ap, ONES, ONES);   // row sums of P
        }
    }
#undef ISSUE_KV

    // lacc[0] = rowsum(g), lacc[2] = rowsum(g+8): all cols identical, no shuffles
    const float hm = headmask[h];
    const float inv0 = hm / lacc[0];
    const float inv1 = hm / lacc[2];
    const int r0 = bS + q0 + warp * 16 + g;
#pragma unroll
    for (int nd = 0; nd < 8; nd++) {
        const int col = h * HDIM + nd * 8 + 2 * tq;
        *(float2*)(out + (size_t)r0 * (2 * AHS) + col) =
            make_float2(o[nd][0] * inv0, o[nd][1] * inv0);
        *(float2*)(out + (size_t)(r0 + 8) * (2 * AHS) + col) =
            make_float2(o[nd][2] * inv1, o[nd][3] * inv1);
    }
}

// ---------------------------------------------------------------------------
extern "C" void kernel_launch(void* const* d_in, const int* in_sizes, int n_in,
                              void* d_out, int out_size)
{
    const float* hs    = (const float*)d_in[0];
    const float* amask = (const float*)d_in[1];
    const float* hmask = (const float*)d_in[2];
    const float* Wq    = (const float*)d_in[3];
    const float* bq    = (const float*)d_in[4];
    const float* Wk    = (const float*)d_in[5];
    const float* bk    = (const float*)d_in[6];
    const float* Wv    = (const float*)d_in[7];
    const float* bv    = (const float*)d_in[8];
    const float* dwk   = (const float*)d_in[9];
    const float* pw    = (const float*)d_in[10];
    const float* cb    = (const float*)d_in[11];
    const float* Wck   = (const float*)d_in[12];
    const float* bck   = (const float*)d_in[13];
    const float* Wco   = (const float*)d_in[14];
    const float* bco   = (const float*)d_in[15];
    float* out = (float*)d_out;

    float *pq, *pco, *pkc, *pdw, *pck;
    unsigned *pkt, *pvtT;
    cudaGetSymbolAddress((void**)&pq,   g_q);
    cudaGetSymbolAddress((void**)&pkt,  g_kt);
    cudaGetSymbolAddress((void**)&pvtT, g_vtT);
    cudaGetSymbolAddress((void**)&pco,  g_co);
    cudaGetSymbolAddress((void**)&pkc,  g_kc);
    cudaGetSymbolAddress((void**)&pdw,  g_dw);
    cudaGetSymbolAddress((void**)&pck,  g_ck);

    cudaFuncSetAttribute(attn_f16, cudaFuncAttributeMaxDynamicSharedMemorySize,
                         (int)sizeof(AttnSmem));
    cudaFuncSetAttribute(span_gemm, cudaFuncAttributeMaxDynamicSharedMemorySize,
                         (int)sizeof(SpanSmem));
    cudaFuncSetAttribute(dynsoft2, cudaFuncAttributeMaxDynamicSharedMemorySize,
                         (int)sizeof(DynSmem));

    // ---- default stream: Q/K/V projections (attn's dependencies) ----
    gemm4_f16<<<dim3(AHS / 64, MROWS / 64, 3), 128>>>(
        hs, Wq, Wk, Wv, Wco, bq, bk, bv, bco, pq, pkt, pvtT, pco, 0);

    // fork: attention on g_s2 overlaps the conv chain
    cudaEventRecord(g_evFork, 0);
    cudaStreamWaitEvent(g_s2, g_evFork, 0);
    attn_f16<<<dim3(SEQ / 128, BATCH * NHEAD), 256, sizeof(AttnSmem), g_s2>>>(
        pq, pkt, pvtT, amask, hmask, out);
    cudaEventRecord(g_evJoin, g_s2);

    // ---- default stream: conv chain ----
    gemm4_f16<<<dim3(AHS / 64, MROWS / 64, 1), 128>>>(
        hs, Wq, Wk, Wv, Wco, bq, bk, bv, bco, pq, pkt, pvtT, pco, 3);
    dwconv9s<<<dim3(CIN / 256, MROWS / 32), 256>>>(hs, dwk, pdw);
    gemm4_f16<<<dim3(AHS / 64, MROWS / 64, 1), 128>>>(
        pdw, pw, pw, pw, pw, cb, cb, cb, cb, pkc, pkt, pvtT, pco, 0);
    span_gemm<<<MROWS / 64, 128, sizeof(SpanSmem)>>>(pkc, pq, Wck, bck, pck);
    dynsoft2<<<MROWS / 32, 384, sizeof(DynSmem)>>>(pck, pco, out);

    // join
    cudaStreamWaitEvent(0, g_evJoin, 0);
}

// round 17
// speedup vs baseline: 1.0512x; 1.0512x over previous
#include <cuda_runtime.h>
#include <cuda_fp16.h>

// ---------------------------------------------------------------------------
// TFConvBertSelfAttention  (B=4, S=2048, C=768, H=6, D=64, AHS=384, K=9)
// R17: conv chain (CO/dwconv/pw) starts at t=0 on stream 2, overlapping the
//      QKV projections; span waits on q via event. Attention = R16 (log2
//      softmax, ex2.f16x2, ones-column l). 
// ---------------------------------------------------------------------------

#define BATCH   4
#define SEQ     2048
#define CIN     768
#define NHEAD   6
#define HDIM    64
#define AHS     384
#define KTAPS   9
#define MROWS   (BATCH * SEQ)          // 8192

// ------------------------- scratch (static device mem) ---------------------
__device__ float    g_q [MROWS * AHS];
__device__ unsigned g_kt[MROWS * (AHS / 2)];
__device__ unsigned g_vtT[AHS * (MROWS / 2)];
__device__ float    g_co[MROWS * AHS];
__device__ float    g_kc[MROWS * AHS];
__device__ float    g_dw[MROWS * CIN];
__device__ float    g_ck[MROWS * 64];

// ------------------------- streams/events (host, created once) -------------
static cudaStream_t g_s2;
static cudaEvent_t  g_evFork, g_evQ, g_evJoin;
namespace {
struct StreamInit {
    StreamInit() {
        cudaStreamCreateWithFlags(&g_s2, cudaStreamNonBlocking);
        cudaEventCreateWithFlags(&g_evFork, cudaEventDisableTiming);
        cudaEventCreateWithFlags(&g_evQ,    cudaEventDisableTiming);
        cudaEventCreateWithFlags(&g_evJoin, cudaEventDisableTiming);
    }
};
static StreamInit g_streamInit;
}

// ------------------------- helpers -----------------------------------------
__device__ __forceinline__ unsigned f2h2(float lo, float hi) {
    unsigned r;
    asm("cvt.rn.f16x2.f32 %0, %1, %2;" : "=r"(r) : "f"(hi), "f"(lo));
    return r;
}

__device__ __forceinline__ unsigned ex2_h2(unsigned x) {
    unsigned r;
    asm("ex2.approx.f16x2 %0, %1;" : "=r"(r) : "r"(x));
    return r;
}

__device__ __forceinline__ void mma_f16(float* c, const unsigned* a,
                                        unsigned b0, unsigned b1) {
    asm volatile(
        "mma.sync.aligned.m16n8k16.row.col.f32.f16.f16.f32 "
        "{%0,%1,%2,%3}, {%4,%5,%6,%7}, {%8,%9}, {%0,%1,%2,%3};\n"
        : "+f"(c[0]), "+f"(c[1]), "+f"(c[2]), "+f"(c[3])
        : "r"(a[0]), "r"(a[1]), "r"(a[2]), "r"(a[3]), "r"(b0), "r"(b1));
}

__device__ __forceinline__ void cpa16(void* sm, const void* g) {
    unsigned sa = (unsigned)__cvta_generic_to_shared(sm);
    asm volatile("cp.async.cg.shared.global [%0], [%1], 16;" :: "r"(sa), "l"(g));
}

// ------------------------- fp16 GEMM, z = blockIdx.z + zbase ----------------
__global__ __launch_bounds__(128)
void gemm4_f16(const float* __restrict__ A,
               const float* __restrict__ W0, const float* __restrict__ W1,
               const float* __restrict__ W2, const float* __restrict__ W3,
               const float* __restrict__ b0, const float* __restrict__ b1,
               const float* __restrict__ b2, const float* __restrict__ b3,
               float* __restrict__ Oq, unsigned* __restrict__ Okt,
               unsigned* __restrict__ OvtT, float* __restrict__ Oco,
               int zbase)
{
    const float* Ws[4] = {W0, W1, W2, W3};
    const float* bs[4] = {b0, b1, b2, b3};
    const int z = blockIdx.z + zbase;
    const float* B = Ws[z];
    const float* bias = bs[z];

    __shared__ unsigned Ash[2][64][20];
    __shared__ unsigned Bsh[2][16][72];

    const int tid  = threadIdx.x;
    const int warp = tid >> 5;
    const int lane = tid & 31;
    const int g    = lane >> 2;
    const int tq   = lane & 3;
    const int m0 = blockIdx.y * 64;
    const int n0 = blockIdx.x * 64;

    float acc[8][4];
#pragma unroll
    for (int nc = 0; nc < 8; nc++)
#pragma unroll
        for (int i = 0; i < 4; i++) acc[nc][i] = 0.f;

    const int a_k4 = (tid & 7) * 4;
    const int a_rb = tid >> 3;
    const int b_kp = tid >> 4;
    const int b_c4 = (tid & 15) * 4;

    float4 ar[4];
    float4 br[2][2];

#pragma unroll
    for (int p = 0; p < 4; p++)
        ar[p] = *(const float4*)(A + (size_t)(m0 + a_rb + 16 * p) * CIN + a_k4);
#pragma unroll
    for (int p = 0; p < 2; p++) {
        const int kp = b_kp + 8 * p;
        br[p][0] = *(const float4*)(B + (size_t)(2 * kp)     * AHS + n0 + b_c4);
        br[p][1] = *(const float4*)(B + (size_t)(2 * kp + 1) * AHS + n0 + b_c4);
    }
#pragma unroll
    for (int p = 0; p < 4; p++) {
        const int row = a_rb + 16 * p;
        Ash[0][row][a_k4 / 2]     = f2h2(ar[p].x, ar[p].y);
        Ash[0][row][a_k4 / 2 + 1] = f2h2(ar[p].z, ar[p].w);
    }
#pragma unroll
    for (int p = 0; p < 2; p++) {
        const int kp = b_kp + 8 * p;
        Bsh[0][kp][b_c4 + 0] = f2h2(br[p][0].x, br[p][1].x);
        Bsh[0][kp][b_c4 + 1] = f2h2(br[p][0].y, br[p][1].y);
        Bsh[0][kp][b_c4 + 2] = f2h2(br[p][0].z, br[p][1].z);
        Bsh[0][kp][b_c4 + 3] = f2h2(br[p][0].w, br[p][1].w);
    }
    __syncthreads();

    const int NIT = CIN / 32;
    for (int it = 0; it < NIT; it++) {
        const int cur = it & 1;
        const bool more = (it + 1 < NIT);

        if (more) {
            const int k0 = (it + 1) * 32;
#pragma unroll
            for (int p = 0; p < 4; p++)
                ar[p] = *(const float4*)(A + (size_t)(m0 + a_rb + 16 * p) * CIN + k0 + a_k4);
#pragma unroll
            for (int p = 0; p < 2; p++) {
                const int kp = b_kp + 8 * p;
                br[p][0] = *(const float4*)(B + (size_t)(k0 + 2 * kp)     * AHS + n0 + b_c4);
                br[p][1] = *(const float4*)(B + (size_t)(k0 + 2 * kp + 1) * AHS + n0 + b_c4);
            }
        }

#pragma unroll
        for (int kcc = 0; kcc < 2; kcc++) {
            unsigned a[4];
            a[0] = Ash[cur][warp * 16 + g    ][kcc * 8 + tq    ];
            a[1] = Ash[cur][warp * 16 + g + 8][kcc * 8 + tq    ];
            a[2] = Ash[cur][warp * 16 + g    ][kcc * 8 + tq + 4];
            a[3] = Ash[cur][warp * 16 + g + 8][kcc * 8 + tq + 4];
#pragma unroll
            for (int nc = 0; nc < 8; nc++)
                mma_f16(acc[nc], a,
                        Bsh[cur][kcc * 8 + tq    ][nc * 8 + g],
                        Bsh[cur][kcc * 8 + tq + 4][nc * 8 + g]);
        }

        if (more) {
            const int nxt = cur ^ 1;
#pragma unroll
            for (int p = 0; p < 4; p++) {
                const int row = a_rb + 16 * p;
                Ash[nxt][row][a_k4 / 2]     = f2h2(ar[p].x, ar[p].y);
                Ash[nxt][row][a_k4 / 2 + 1] = f2h2(ar[p].z, ar[p].w);
            }
#pragma unroll
            for (int p = 0; p < 2; p++) {
                const int kp = b_kp + 8 * p;
                Bsh[nxt][kp][b_c4 + 0] = f2h2(br[p][0].x, br[p][1].x);
                Bsh[nxt][kp][b_c4 + 1] = f2h2(br[p][0].y, br[p][1].y);
                Bsh[nxt][kp][b_c4 + 2] = f2h2(br[p][0].z, br[p][1].z);
                Bsh[nxt][kp][b_c4 + 3] = f2h2(br[p][0].w, br[p][1].w);
            }
        }
        __syncthreads();
    }

    const int r0 = m0 + warp * 16 + g;
    if (z == 0 || z == 3) {
        float* C = (z == 0) ? Oq : Oco;
#pragma unroll
        for (int nc = 0; nc < 8; nc++) {
            const int col = n0 + nc * 8 + 2 * tq;
            const float bv0 = bias[col], bv1 = bias[col + 1];
            *(float2*)(C + (size_t)r0 * AHS + col) =
                make_float2(acc[nc][0] + bv0, acc[nc][1] + bv1);
            *(float2*)(C + (size_t)(r0 + 8) * AHS + col) =
                make_float2(acc[nc][2] + bv0, acc[nc][3] + bv1);
        }
    } else if (z == 1) {
#pragma unroll
        for (int nc = 0; nc < 8; nc++) {
            const int col = n0 + nc * 8 + 2 * tq;
            const float bv0 = bias[col], bv1 = bias[col + 1];
            const int wp = n0 / 2 + (nc >> 1) * 8 + 2 * tq + (nc & 1);
            Okt[(size_t)r0 * (AHS / 2) + wp]       = f2h2(acc[nc][0] + bv0, acc[nc][1] + bv1);
            Okt[(size_t)(r0 + 8) * (AHS / 2) + wp] = f2h2(acc[nc][2] + bv0, acc[nc][3] + bv1);
        }
    } else {
#pragma unroll
        for (int nc = 0; nc < 8; nc++) {
            const int col = n0 + nc * 8 + 2 * tq;
            const float bv0 = bias[col], bv1 = bias[col + 1];
            const unsigned ulo = f2h2(acc[nc][0] + bv0, acc[nc][1] + bv1);
            const unsigned uhi = f2h2(acc[nc][2] + bv0, acc[nc][3] + bv1);
            const unsigned plo = __shfl_xor_sync(0xffffffffu, ulo, 4);
            const unsigned phi = __shfl_xor_sync(0xffffffffu, uhi, 4);
            if ((g & 1) == 0) {
                const unsigned w0lo = (ulo & 0xFFFFu) | (plo << 16);
                const unsigned w1lo = (ulo >> 16)     | (plo & 0xFFFF0000u);
                const unsigned w0hi = (uhi & 0xFFFFu) | (phi << 16);
                const unsigned w1hi = (uhi >> 16)     | (phi & 0xFFFF0000u);
                const size_t base = (size_t)(m0 / 2 + warp * 8 + g);
                *(uint2*)(OvtT + (size_t)col * (MROWS / 2) + base) =
                    make_uint2(w0lo, w0hi);
                *(uint2*)(OvtT + (size_t)(col + 1) * (MROWS / 2) + base) =
                    make_uint2(w1lo, w1hi);
            }
        }
    }
}

// ------------------------- depthwise conv, smem tiled ----------------------
__global__ __launch_bounds__(256)
void dwconv9s(const float* __restrict__ hs, const float* __restrict__ w,
              float* __restrict__ out)
{
    __shared__ float tile[40][256];
    const int tid = threadIdx.x;
    const int c0  = blockIdx.x * 256;
    const int row0 = blockIdx.y * 32;
    const int b = row0 >> 11;
    const int s0 = row0 & (SEQ - 1);

    for (int i = tid; i < 40 * 256; i += 256) {
        const int r = i >> 8, c = i & 255;
        const int ss = s0 + r - 4;
        tile[r][c] = (ss >= 0 && ss < SEQ)
            ? hs[(size_t)(b * SEQ + ss) * CIN + c0 + c] : 0.f;
    }
    float wr[KTAPS];
#pragma unroll
    for (int t = 0; t < KTAPS; t++) wr[t] = w[t * CIN + c0 + tid];
    __syncthreads();

#pragma unroll 4
    for (int si = 0; si < 32; si++) {
        float acc = 0.f;
#pragma unroll
        for (int t = 0; t < KTAPS; t++)
            acc = fmaf(tile[si + t][tid], wr[t], acc);
        out[(size_t)(row0 + si) * CIN + c0 + tid] = acc;
    }
}

// ---------------- span GEMM: logits = (kc*q) @ Wck + bck -------------------
struct SpanSmem {
    unsigned As[64][20];
    unsigned Bw[192][56];
};

__global__ __launch_bounds__(128)
void span_gemm(const float* __restrict__ kcv, const float* __restrict__ q,
               const float* __restrict__ Wck, const float* __restrict__ bck,
               float* __restrict__ ck)
{
    extern __shared__ char smem_raw[];
    SpanSmem& sm = *reinterpret_cast<SpanSmem*>(smem_raw);

    const int tid  = threadIdx.x;
    const int warp = tid >> 5;
    const int lane = tid & 31;
    const int g    = lane >> 2;
    const int tq   = lane & 3;
    const int m0 = blockIdx.x * 64;
    const int NCK = NHEAD * KTAPS;   // 54

    for (int idx = tid; idx < 192 * NCK; idx += 128) {
        const int kp = idx / NCK, c = idx % NCK;
        sm.Bw[kp][c] = f2h2(Wck[(size_t)(2 * kp) * NCK + c],
                            Wck[(size_t)(2 * kp + 1) * NCK + c]);
    }
    for (int idx = tid; idx < 192 * 2; idx += 128)
        sm.Bw[idx >> 1][54 + (idx & 1)] = 0u;

    float acc[7][4];
#pragma unroll
    for (int nc = 0; nc < 7; nc++)
#pragma unroll
        for (int i = 0; i < 4; i++) acc[nc][i] = 0.f;

    const int a_k4 = (tid & 7) * 4;
    const int a_rb = tid >> 3;

    float4 xr[4], qr[4];
#pragma unroll
    for (int p = 0; p < 4; p++) {
        const size_t off = (size_t)(m0 + a_rb + 16 * p) * AHS + a_k4;
        xr[p] = *(const float4*)(kcv + off);
        qr[p] = *(const float4*)(q + off);
    }

    for (int k0 = 0; k0 < AHS; k0 += 32) {
#pragma unroll
        for (int p = 0; p < 4; p++) {
            const int row = a_rb + 16 * p;
            sm.As[row][a_k4 / 2]     = f2h2(xr[p].x * qr[p].x, xr[p].y * qr[p].y);
            sm.As[row][a_k4 / 2 + 1] = f2h2(xr[p].z * qr[p].z, xr[p].w * qr[p].w);
        }
        __syncthreads();

        if (k0 + 32 < AHS) {
#pragma unroll
            for (int p = 0; p < 4; p++) {
                const size_t off = (size_t)(m0 + a_rb + 16 * p) * AHS + k0 + 32 + a_k4;
                xr[p] = *(const float4*)(kcv + off);
                qr[p] = *(const float4*)(q + off);
            }
        }

#pragma unroll
        for (int kcc = 0; kcc < 2; kcc++) {
            unsigned a[4];
            a[0] = sm.As[warp * 16 + g    ][kcc * 8 + tq    ];
            a[1] = sm.As[warp * 16 + g + 8][kcc * 8 + tq    ];
            a[2] = sm.As[warp * 16 + g    ][kcc * 8 + tq + 4];
            a[3] = sm.As[warp * 16 + g + 8][kcc * 8 + tq + 4];
            const int kpb = k0 / 2 + kcc * 8;
#pragma unroll
            for (int nc = 0; nc < 7; nc++)
                mma_f16(acc[nc], a,
                        sm.Bw[kpb + tq    ][nc * 8 + g],
                        sm.Bw[kpb + tq + 4][nc * 8 + g]);
        }
        __syncthreads();
    }

    const int r0 = m0 + warp * 16 + g;
#pragma unroll
    for (int nc = 0; nc < 7; nc++) {
        const int col = nc * 8 + 2 * tq;
        if (col < NCK) {
            const float bv0 = bck[col], bv1 = bck[col + 1];
            ck[(size_t)r0 * 64 + col]           = acc[nc][0] + bv0;
            ck[(size_t)r0 * 64 + col + 1]       = acc[nc][1] + bv1;
            ck[(size_t)(r0 + 8) * 64 + col]     = acc[nc][2] + bv0;
            ck[(size_t)(r0 + 8) * 64 + col + 1] = acc[nc][3] + bv1;
        }
    }
}

// ---------------- softmax + dynamic conv (smem tiled) ----------------------
struct DynSmem {
    float cot[40][384];
    float p[32][56];
};

__global__ __launch_bounds__(384)
void dynsoft2(const float* __restrict__ ckraw, const float* __restrict__ co,
              float* __restrict__ out)
{
    extern __shared__ char smem_raw[];
    DynSmem& sm = *reinterpret_cast<DynSmem*>(smem_raw);
    const int tid = threadIdx.x;
    const int row0 = blockIdx.x * 32;
    const int b = row0 >> 11;
    const int s0 = row0 & (SEQ - 1);

    for (int j = 0; j < 40; j++) {
        const int ss = s0 + j - 4;
        sm.cot[j][tid] = (ss >= 0 && ss < SEQ)
            ? co[(size_t)(b * SEQ + ss) * AHS + tid] : 0.f;
    }
    if (tid < 32 * NHEAD) {
        const int r = tid / NHEAD, h = tid % NHEAD;
        const float* lr = ckraw + (size_t)(row0 + r) * 64 + h * KTAPS;
        float m = -1e30f;
#pragma unroll
        for (int t = 0; t < KTAPS; t++) m = fmaxf(m, lr[t]);
        float e[KTAPS], s = 0.f;
#pragma unroll
        for (int t = 0; t < KTAPS; t++) { e[t] = __expf(lr[t] - m); s += e[t]; }
        const float inv = 1.f / s;
#pragma unroll
        for (int t = 0; t < KTAPS; t++) sm.p[r][h * KTAPS + t] = e[t] * inv;
    }
    __syncthreads();

    const int h = tid >> 6;
#pragma unroll 4
    for (int si = 0; si < 32; si++) {
        float acc = 0.f;
#pragma unroll
        for (int t = 0; t < KTAPS; t++)
            acc = fmaf(sm.p[si][h * KTAPS + t], sm.cot[si + t][tid], acc);
        out[(size_t)(row0 + si) * (2 * AHS) + AHS + tid] = acc;
    }
}

// ---------------- flash attention (fp16 mma, log2-domain softmax) ----------
struct AttnSmem {
    unsigned Ks[2][64][40];
    unsigned Vs[2][64][40];
    float    Ms[SEQ];
};

__global__ __launch_bounds__(256, 2)
void attn_f16(const float* __restrict__ q, const unsigned* __restrict__ kt,
              const unsigned* __restrict__ vtT, const float* __restrict__ mask,
              const float* __restrict__ headmask, float* __restrict__ out)
{
    extern __shared__ char smem_raw[];
    AttnSmem& sm = *reinterpret_cast<AttnSmem*>(smem_raw);

    const int tid  = threadIdx.x;
    const int warp = tid >> 5;
    const int lane = tid & 31;
    const int g    = lane >> 2;
    const int tq   = lane & 3;

    const int bh = blockIdx.y;
    const int b = bh / NHEAD, h = bh % NHEAD;
    const int q0 = blockIdx.x * 128;
    const int bS = b * SEQ;

    const float LOG2E = 1.4426950408889634f;

    for (int i = tid; i < SEQ; i += 256)
        sm.Ms[i] = mask[(size_t)bS + i] * LOG2E;

    unsigned aq[4][4];
    {
        const float* qp = q + (size_t)(bS + q0 + warp * 16) * AHS + h * HDIM;
        const float s = 0.125f * LOG2E;
#pragma unroll
        for (int kc = 0; kc < 4; kc++) {
            const int c0 = kc * 16 + 2 * tq;
            aq[kc][0] = f2h2(qp[(size_t)g       * AHS + c0]     * s, qp[(size_t)g       * AHS + c0 + 1] * s);
            aq[kc][1] = f2h2(qp[(size_t)(g + 8) * AHS + c0]     * s, qp[(size_t)(g + 8) * AHS + c0 + 1] * s);
            aq[kc][2] = f2h2(qp[(size_t)g       * AHS + c0 + 8] * s, qp[(size_t)g       * AHS + c0 + 9] * s);
            aq[kc][3] = f2h2(qp[(size_t)(g + 8) * AHS + c0 + 8] * s, qp[(size_t)(g + 8) * AHS + c0 + 9] * s);
        }
    }

    float o[8][4];
#pragma unroll
    for (int nc = 0; nc < 8; nc++)
#pragma unroll
        for (int i = 0; i < 4; i++) o[nc][i] = 0.f;
    float lacc[4] = {0.f, 0.f, 0.f, 0.f};
    const unsigned ONES = 0x3C003C00u;

#define ISSUE_KV(ibv, kbv) do {                                                  \
        _Pragma("unroll")                                                        \
        for (int cc = 0; cc < 2; cc++) {                                         \
            const int ch = tid + cc * 256;                                       \
            const int rr = ch >> 3, seg = (ch & 7) * 4;                          \
            cpa16(&sm.Ks[ibv][rr][seg],                                          \
                  kt + (size_t)(bS + (kbv) + rr) * (AHS / 2) + h * 32 + seg);    \
            cpa16(&sm.Vs[ibv][rr][seg],                                          \
                  vtT + (size_t)(h * 64 + rr) * (MROWS / 2) + (bS + (kbv)) / 2 + seg); \
        }                                                                        \
        asm volatile("cp.async.commit_group;");                                  \
    } while (0)

    ISSUE_KV(0, 0);

    for (int kb = 0; kb < SEQ; kb += 64) {
        asm volatile("cp.async.wait_group 0;");
        __syncthreads();
        const int ibuf = (kb >> 6) & 1;
        if (kb + 64 < SEQ) ISSUE_KV(ibuf ^ 1, kb + 64);

        float sfr[8][4];
#pragma unroll
        for (int nc = 0; nc < 8; nc++) {
            sfr[nc][0] = sfr[nc][1] = sfr[nc][2] = sfr[nc][3] = 0.f;
#pragma unroll
            for (int kc = 0; kc < 4; kc++) {
                uint2 bb = *(const uint2*)&sm.Ks[ibuf][nc * 8 + g][kc * 8 + 2 * tq];
                mma_f16(sfr[nc], aq[kc], bb.x, bb.y);
            }
            float2 mv = *(const float2*)&sm.Ms[kb + nc * 8 + 2 * tq];
            sfr[nc][0] += mv.x; sfr[nc][1] += mv.y;
            sfr[nc][2] += mv.x; sfr[nc][3] += mv.y;
        }

        unsigned Pu0[8], Pu1[8];
#pragma unroll
        for (int nc = 0; nc < 8; nc++) {
            Pu0[nc] = ex2_h2(f2h2(sfr[nc][0], sfr[nc][1]));
            Pu1[nc] = ex2_h2(f2h2(sfr[nc][2], sfr[nc][3]));
        }

#pragma unroll
        for (int kc = 0; kc < 4; kc++) {
            unsigned ap[4];
            ap[0] = Pu0[2 * kc];
            ap[1] = Pu1[2 * kc];
            ap[2] = Pu0[2 * kc + 1];
            ap[3] = Pu1[2 * kc + 1];
#pragma unroll
            for (int nd = 0; nd < 8; nd++) {
                uint2 vv = *(const uint2*)&sm.Vs[ibuf][nd * 8 + g][kc * 8 + 2 * tq];
                mma_f16(o[nd], ap, vv.x, vv.y);
            }
            mma_f16(lacc, ap, ONES, ONES);
        }
    }
#undef ISSUE_KV

    const float hm = headmask[h];
    const float inv0 = hm / lacc[0];
    const float inv1 = hm / lacc[2];
    const int r0 = bS + q0 + warp * 16 + g;
#pragma unroll
    for (int nd = 0; nd < 8; nd++) {
        const int col = h * HDIM + nd * 8 + 2 * tq;
        *(float2*)(out + (size_t)r0 * (2 * AHS) + col) =
            make_float2(o[nd][0] * inv0, o[nd][1] * inv0);
        *(float2*)(out + (size_t)(r0 + 8) * (2 * AHS) + col) =
            make_float2(o[nd][2] * inv1, o[nd][3] * inv1);
    }
}

// ---------------------------------------------------------------------------
extern "C" void kernel_launch(void* const* d_in, const int* in_sizes, int n_in,
                              void* d_out, int out_size)
{
    const float* hs    = (const float*)d_in[0];
    const float* amask = (const float*)d_in[1];
    const float* hmask = (const float*)d_in[2];
    const float* Wq    = (const float*)d_in[3];
    const float* bq    = (const float*)d_in[4];
    const float* Wk    = (const float*)d_in[5];
    const float* bk    = (const float*)d_in[6];
    const float* Wv    = (const float*)d_in[7];
    const float* bv    = (const float*)d_in[8];
    const float* dwk   = (const float*)d_in[9];
    const float* pw    = (const float*)d_in[10];
    const float* cb    = (const float*)d_in[11];
    const float* Wck   = (const float*)d_in[12];
    const float* bck   = (const float*)d_in[13];
    const float* Wco   = (const float*)d_in[14];
    const float* bco   = (const float*)d_in[15];
    float* out = (float*)d_out;

    float *pq, *pco, *pkc, *pdw, *pck;
    unsigned *pkt, *pvtT;
    cudaGetSymbolAddress((void**)&pq,   g_q);
    cudaGetSymbolAddress((void**)&pkt,  g_kt);
    cudaGetSymbolAddress((void**)&pvtT, g_vtT);
    cudaGetSymbolAddress((void**)&pco,  g_co);
    cudaGetSymbolAddress((void**)&pkc,  g_kc);
    cudaGetSymbolAddress((void**)&pdw,  g_dw);
    cudaGetSymbolAddress((void**)&pck,  g_ck);

    cudaFuncSetAttribute(attn_f16, cudaFuncAttributeMaxDynamicSharedMemorySize,
                         (int)sizeof(AttnSmem));
    cudaFuncSetAttribute(span_gemm, cudaFuncAttributeMaxDynamicSharedMemorySize,
                         (int)sizeof(SpanSmem));
    cudaFuncSetAttribute(dynsoft2, cudaFuncAttributeMaxDynamicSharedMemorySize,
                         (int)sizeof(DynSmem));

    // fork at t=0: s2 runs the hs-only conv prefix concurrently with QKV
    cudaEventRecord(g_evFork, 0);
    cudaStreamWaitEvent(g_s2, g_evFork, 0);

    // ---- s2: conv prefix (depends only on hs) ----
    gemm4_f16<<<dim3(AHS / 64, MROWS / 64, 1), 128, 0, g_s2>>>(
        hs, Wq, Wk, Wv, Wco, bq, bk, bv, bco, pq, pkt, pvtT, pco, 3);   // CO
    dwconv9s<<<dim3(CIN / 256, MROWS / 32), 256, 0, g_s2>>>(hs, dwk, pdw);
    gemm4_f16<<<dim3(AHS / 64, MROWS / 64, 1), 128, 0, g_s2>>>(
        pdw, pw, pw, pw, pw, cb, cb, cb, cb, pkc, pkt, pvtT, pco, 0);   // pw

    // ---- default: Q/K/V projections ----
    gemm4_f16<<<dim3(AHS / 64, MROWS / 64, 3), 128>>>(
        hs, Wq, Wk, Wv, Wco, bq, bk, bv, bco, pq, pkt, pvtT, pco, 0);
    cudaEventRecord(g_evQ, 0);

    // ---- default: attention (needs q/kt/vtT) ----
    attn_f16<<<dim3(SEQ / 128, BATCH * NHEAD), 256, sizeof(AttnSmem)>>>(
        pq, pkt, pvtT, amask, hmask, out);

    // ---- s2: span (needs q) + dynsoft ----
    cudaStreamWaitEvent(g_s2, g_evQ, 0);
    span_gemm<<<MROWS / 64, 128, sizeof(SpanSmem), g_s2>>>(pkc, pq, Wck, bck, pck);
    dynsoft2<<<MROWS / 32, 384, sizeof(DynSmem), g_s2>>>(pck, pco, out);
    cudaEventRecord(g_evJoin, g_s2);

    // join
    cudaStreamWaitEvent(0, g_evJoin, 0);
}